// round 2
// baseline (speedup 1.0000x reference)
#include <cuda_runtime.h>
#include <cstdint>

#define N_NODES 50000
#define N_EDGES 800000
#define N_RELS  200
#define D       128
#define D4      (D/4)

// Scratch (allocation-free rule: __device__ globals)
__device__ float g_hn[N_NODES * D];   // h * norm
__device__ float g_agg[N_NODES * D];  // segment_sum(hn[src] - r[rel], dst)

// ---------------------------------------------------------------------------
// Kernel 1: hn = h * norm ; agg = 0
// ---------------------------------------------------------------------------
__global__ void k_prep(const float* __restrict__ h, const float* __restrict__ norm) {
    int i = blockIdx.x * blockDim.x + threadIdx.x;   // float4 index
    if (i >= N_NODES * D4) return;
    int row = i / D4;
    float n = __ldg(norm + row);
    float4 v = reinterpret_cast<const float4*>(h)[i];
    v.x *= n; v.y *= n; v.z *= n; v.w *= n;
    reinterpret_cast<float4*>(g_hn)[i] = v;
    reinterpret_cast<float4*>(g_agg)[i] = make_float4(0.f, 0.f, 0.f, 0.f);
}

// ---------------------------------------------------------------------------
// Kernel 2: per-edge scatter-add:  agg[dst] += hn[src] - r[rel]
// One warp per edge; lane l handles float4 chunk l (D=128 -> 32 chunks).
// Vector reduction (red.global.add.v4.f32, sm_90+) quarters atomic op count.
// ---------------------------------------------------------------------------
__global__ void k_edge(const float* __restrict__ r,
                       const int* __restrict__ src,
                       const int* __restrict__ dst,
                       const int* __restrict__ rel) {
    int warp = (blockIdx.x * blockDim.x + threadIdx.x) >> 5;
    int lane = threadIdx.x & 31;
    if (warp >= N_EDGES) return;

    int s  = __ldg(src + warp);
    int d  = __ldg(dst + warp);
    int rl = __ldg(rel + warp);

    float4 hv = __ldg(reinterpret_cast<const float4*>(g_hn) + s * D4 + lane);
    float4 rv = __ldg(reinterpret_cast<const float4*>(r)    + rl * D4 + lane);

    float4 m = make_float4(hv.x - rv.x, hv.y - rv.y, hv.z - rv.z, hv.w - rv.w);
    float4* p = reinterpret_cast<float4*>(g_agg) + d * D4 + lane;
    asm volatile("red.global.add.v4.f32 [%0], {%1, %2, %3, %4};"
                 :: "l"(p), "f"(m.x), "f"(m.y), "f"(m.z), "f"(m.w)
                 : "memory");
}

// ---------------------------------------------------------------------------
// Kernel 3: out = relu( hn @ W + (agg * norm) @ W_msg + b )
// Treated as one [N, 256] @ [256, 128] GEMM with the stacked weight
// Wc = [W ; W_msg] (256x128, 128 KB) resident in smem per block.
// Tile: 64 rows x 128 cols per block, 256 threads, 4 rows x 8 cols per thread.
// A tile stored transposed sA[k][row] (ld=65 to kill bank conflicts).
// ---------------------------------------------------------------------------
#define MT     64
#define SA_LD  65
#define SMEM_GEMM ((256 * 128 + 256 * SA_LD) * (int)sizeof(float))  // 197,632 B

__global__ __launch_bounds__(256, 1)
void k_gemm(const float* __restrict__ norm,
            const float* __restrict__ W_msg,
            const float* __restrict__ W,
            const float* __restrict__ b,
            float* __restrict__ out) {
    extern __shared__ float smem[];
    float* sW = smem;              // [256][128]
    float* sA = smem + 256 * 128;  // [256][SA_LD]

    const int tid = threadIdx.x;
    const int tileBase = blockIdx.x * MT;

    // --- load stacked weights: rows 0..127 = W, 128..255 = W_msg ---
    {
        const float4* W4  = reinterpret_cast<const float4*>(W);
        const float4* Wm4 = reinterpret_cast<const float4*>(W_msg);
        float4* sW4 = reinterpret_cast<float4*>(sW);
        #pragma unroll
        for (int i = tid; i < 256 * 32; i += 256)
            sW4[i] = (i < 128 * 32) ? __ldg(W4 + i) : __ldg(Wm4 + (i - 128 * 32));
    }

    // --- load A tile transposed: k 0..127 = hn, k 128..255 = agg*norm ---
    for (int i = tid; i < MT * 32; i += 256) {
        int rr = i / 32;              // local row 0..63
        int k4 = i % 32;              // float4 index along k
        int row = tileBase + rr;
        float4 v = make_float4(0.f, 0.f, 0.f, 0.f);
        if (row < N_NODES) v = reinterpret_cast<const float4*>(g_hn)[row * D4 + k4];
        sA[(k4 * 4 + 0) * SA_LD + rr] = v.x;
        sA[(k4 * 4 + 1) * SA_LD + rr] = v.y;
        sA[(k4 * 4 + 2) * SA_LD + rr] = v.z;
        sA[(k4 * 4 + 3) * SA_LD + rr] = v.w;
    }
    for (int i = tid; i < MT * 32; i += 256) {
        int rr = i / 32;
        int k4 = i % 32;
        int row = tileBase + rr;
        float4 v = make_float4(0.f, 0.f, 0.f, 0.f);
        float nm = 0.f;
        if (row < N_NODES) {
            v = reinterpret_cast<const float4*>(g_agg)[row * D4 + k4];
            nm = __ldg(norm + row);
        }
        sA[(128 + k4 * 4 + 0) * SA_LD + rr] = v.x * nm;
        sA[(128 + k4 * 4 + 1) * SA_LD + rr] = v.y * nm;
        sA[(128 + k4 * 4 + 2) * SA_LD + rr] = v.z * nm;
        sA[(128 + k4 * 4 + 3) * SA_LD + rr] = v.w * nm;
    }
    __syncthreads();

    // --- microkernel: thread (tcol, trow) owns rows r0..r0+3,
    //     cols {tcol*4..+3} and {64 + tcol*4..+3} (both halves conflict-free) ---
    const int tcol = tid & 15;
    const int trow = tid >> 4;
    const int r0 = trow * 4;

    float acc[2][4][4];
    #pragma unroll
    for (int j = 0; j < 2; j++)
        #pragma unroll
        for (int rr = 0; rr < 4; rr++)
            #pragma unroll
            for (int cc = 0; cc < 4; cc++) acc[j][rr][cc] = 0.f;

    #pragma unroll 8
    for (int k = 0; k < 256; k++) {
        float4 w0 = *reinterpret_cast<const float4*>(&sW[k * 128 + tcol * 4]);
        float4 w1 = *reinterpret_cast<const float4*>(&sW[k * 128 + 64 + tcol * 4]);
        float a0 = sA[k * SA_LD + r0 + 0];
        float a1 = sA[k * SA_LD + r0 + 1];
        float a2 = sA[k * SA_LD + r0 + 2];
        float a3 = sA[k * SA_LD + r0 + 3];
        float av[4] = {a0, a1, a2, a3};
        #pragma unroll
        for (int rr = 0; rr < 4; rr++) {
            acc[0][rr][0] += av[rr] * w0.x;
            acc[0][rr][1] += av[rr] * w0.y;
            acc[0][rr][2] += av[rr] * w0.z;
            acc[0][rr][3] += av[rr] * w0.w;
            acc[1][rr][0] += av[rr] * w1.x;
            acc[1][rr][1] += av[rr] * w1.y;
            acc[1][rr][2] += av[rr] * w1.z;
            acc[1][rr][3] += av[rr] * w1.w;
        }
    }

    // --- epilogue: + b, relu, store ---
    #pragma unroll
    for (int j = 0; j < 2; j++) {
        int cbase = j * 64 + tcol * 4;
        float4 bb = __ldg(reinterpret_cast<const float4*>(b) + cbase / 4);
        #pragma unroll
        for (int rr = 0; rr < 4; rr++) {
            int row = tileBase + r0 + rr;
            if (row < N_NODES) {
                float4 o;
                o.x = fmaxf(acc[j][rr][0] + bb.x, 0.f);
                o.y = fmaxf(acc[j][rr][1] + bb.y, 0.f);
                o.z = fmaxf(acc[j][rr][2] + bb.z, 0.f);
                o.w = fmaxf(acc[j][rr][3] + bb.w, 0.f);
                reinterpret_cast<float4*>(out)[row * D4 + cbase / 4] = o;
            }
        }
    }
}

// ---------------------------------------------------------------------------
extern "C" void kernel_launch(void* const* d_in, const int* in_sizes, int n_in,
                              void* d_out, int out_size) {
    const float* h     = (const float*)d_in[0];
    const float* r     = (const float*)d_in[1];
    const float* norm  = (const float*)d_in[2];
    const int*   src   = (const int*)d_in[3];
    const int*   dst   = (const int*)d_in[4];
    const int*   rel   = (const int*)d_in[5];
    const float* W_msg = (const float*)d_in[6];
    const float* W     = (const float*)d_in[7];
    const float* b     = (const float*)d_in[8];
    float* out = (float*)d_out;

    // prep: hn = h*norm, agg = 0
    {
        int total = N_NODES * D4;
        k_prep<<<(total + 255) / 256, 256>>>(h, norm);
    }
    // edge scatter: one warp per edge, 8 warps per block
    k_edge<<<(N_EDGES + 7) / 8, 256>>>(r, src, dst, rel);

    // fused GEMM + epilogue
    cudaFuncSetAttribute(k_gemm, cudaFuncAttributeMaxDynamicSharedMemorySize, SMEM_GEMM);
    k_gemm<<<(N_NODES + MT - 1) / MT, 256, SMEM_GEMM>>>(norm, W_msg, W, b, out);
}

// round 3
// speedup vs baseline: 1.1929x; 1.1929x over previous
#include <cuda_runtime.h>
#include <cstdint>

#define N_NODES 50000
#define N_EDGES 800000
#define N_RELS  200
#define D       128
#define D4      (D/4)

#define SCAN_CHUNK 1024
#define N_CHUNKS   ((N_NODES + SCAN_CHUNK - 1) / SCAN_CHUNK)   // 49

// Scratch (allocation-free rule: __device__ globals)
__device__ float g_hn[N_NODES * D];    // h * norm
__device__ float g_agg[N_NODES * D];   // (segment_sum(hn[src]-r[rel], dst)) * norm
__device__ int   g_cnt[N_NODES];       // per-dst degree
__device__ int   g_off[N_NODES + 1];   // CSR offsets
__device__ int   g_cur[N_NODES];       // running fill cursors
__device__ int   g_ekey[N_EDGES];      // packed (src<<8)|rel, bucketed by dst
__device__ int   g_bsum[64];           // scan block sums

// ---------------------------------------------------------------------------
// f32x2 helpers (packed FFMA — PTX-only, ptxas never auto-fuses)
// ---------------------------------------------------------------------------
typedef unsigned long long u64;

__device__ __forceinline__ u64 pack_dup(float x) {
    unsigned r = __float_as_uint(x);
    u64 d;
    asm("mov.b64 %0, {%1, %1};" : "=l"(d) : "r"(r));
    return d;
}
__device__ __forceinline__ u64 ffma2(u64 a, u64 b, u64 c) {
    u64 d;
    asm("fma.rn.f32x2 %0, %1, %2, %3;" : "=l"(d) : "l"(a), "l"(b), "l"(c));
    return d;
}
__device__ __forceinline__ float2 unpack2(u64 p) {
    unsigned lo, hi;
    asm("mov.b64 {%0, %1}, %2;" : "=r"(lo), "=r"(hi) : "l"(p));
    return make_float2(__uint_as_float(lo), __uint_as_float(hi));
}

// ---------------------------------------------------------------------------
// Kernel 1: hn = h * norm ; zero degree counters
// ---------------------------------------------------------------------------
__global__ void k_prep(const float* __restrict__ h, const float* __restrict__ norm) {
    int i = blockIdx.x * blockDim.x + threadIdx.x;   // float4 index
    if (i < N_NODES) g_cnt[i] = 0;
    if (i >= N_NODES * D4) return;
    int row = i / D4;
    float n = __ldg(norm + row);
    float4 v = reinterpret_cast<const float4*>(h)[i];
    v.x *= n; v.y *= n; v.z *= n; v.w *= n;
    reinterpret_cast<float4*>(g_hn)[i] = v;
}

// ---------------------------------------------------------------------------
// CSR build: histogram -> scan -> fill
// ---------------------------------------------------------------------------
__global__ void k_hist(const int* __restrict__ dst) {
    int e = blockIdx.x * blockDim.x + threadIdx.x;
    if (e < N_EDGES) atomicAdd(&g_cnt[__ldg(dst + e)], 1);
}

__global__ void k_scan1() {
    __shared__ int s[SCAN_CHUNK];
    int tid = threadIdx.x;
    int idx = blockIdx.x * SCAN_CHUNK + tid;
    int v = (idx < N_NODES) ? g_cnt[idx] : 0;
    s[tid] = v;
    __syncthreads();
    #pragma unroll
    for (int ofs = 1; ofs < SCAN_CHUNK; ofs <<= 1) {
        int t = (tid >= ofs) ? s[tid - ofs] : 0;
        __syncthreads();
        s[tid] += t;
        __syncthreads();
    }
    if (idx < N_NODES) g_off[idx] = s[tid] - v;            // exclusive (partial)
    if (tid == SCAN_CHUNK - 1) g_bsum[blockIdx.x] = s[tid];
}

__global__ void k_scan2() {
    if (threadIdx.x == 0) {
        int acc = 0;
        for (int i = 0; i < N_CHUNKS; i++) {
            int v = g_bsum[i];
            g_bsum[i] = acc;
            acc += v;
        }
    }
}

__global__ void k_scan3() {
    int idx = blockIdx.x * SCAN_CHUNK + threadIdx.x;
    if (idx < N_NODES) {
        int o = g_off[idx] + g_bsum[blockIdx.x];
        g_off[idx] = o;
        g_cur[idx] = o;
    }
    if (idx == 0) g_off[N_NODES] = N_EDGES;
}

__global__ void k_fill(const int* __restrict__ src,
                       const int* __restrict__ dst,
                       const int* __restrict__ rel) {
    int e = blockIdx.x * blockDim.x + threadIdx.x;
    if (e >= N_EDGES) return;
    int d = __ldg(dst + e);
    int pos = atomicAdd(&g_cur[d], 1);
    g_ekey[pos] = (__ldg(src + e) << 8) | __ldg(rel + e);
}

// ---------------------------------------------------------------------------
// Kernel: gather — one warp per dst node, register accumulation, no atomics.
//   g_agg[n] = norm[n] * sum_{e in CSR[n]} (hn[src_e] - r[rel_e])
// ---------------------------------------------------------------------------
__global__ void k_gather(const float* __restrict__ r,
                         const float* __restrict__ norm) {
    int warp = (blockIdx.x * blockDim.x + threadIdx.x) >> 5;
    int lane = threadIdx.x & 31;
    if (warp >= N_NODES) return;

    int e0 = __ldg(g_off + warp);
    int e1 = __ldg(g_off + warp + 1);

    const float4* hn4 = reinterpret_cast<const float4*>(g_hn);
    const float4* r4  = reinterpret_cast<const float4*>(r);

    float4 acc0 = make_float4(0.f, 0.f, 0.f, 0.f);
    float4 acc1 = make_float4(0.f, 0.f, 0.f, 0.f);

    int e = e0;
    for (; e + 2 <= e1; e += 2) {
        int k0 = __ldg(g_ekey + e);
        int k1 = __ldg(g_ekey + e + 1);
        float4 h0 = __ldg(hn4 + (k0 >> 8) * D4 + lane);
        float4 v0 = __ldg(r4  + (k0 & 255) * D4 + lane);
        float4 h1 = __ldg(hn4 + (k1 >> 8) * D4 + lane);
        float4 v1 = __ldg(r4  + (k1 & 255) * D4 + lane);
        acc0.x += h0.x - v0.x; acc0.y += h0.y - v0.y;
        acc0.z += h0.z - v0.z; acc0.w += h0.w - v0.w;
        acc1.x += h1.x - v1.x; acc1.y += h1.y - v1.y;
        acc1.z += h1.z - v1.z; acc1.w += h1.w - v1.w;
    }
    if (e < e1) {
        int k0 = __ldg(g_ekey + e);
        float4 h0 = __ldg(hn4 + (k0 >> 8) * D4 + lane);
        float4 v0 = __ldg(r4  + (k0 & 255) * D4 + lane);
        acc0.x += h0.x - v0.x; acc0.y += h0.y - v0.y;
        acc0.z += h0.z - v0.z; acc0.w += h0.w - v0.w;
    }

    float nm = __ldg(norm + warp);
    float4 o;
    o.x = (acc0.x + acc1.x) * nm;
    o.y = (acc0.y + acc1.y) * nm;
    o.z = (acc0.z + acc1.z) * nm;
    o.w = (acc0.w + acc1.w) * nm;
    reinterpret_cast<float4*>(g_agg)[warp * D4 + lane] = o;
}

// ---------------------------------------------------------------------------
// Kernel: GEMM  out = relu( [hn | agg] @ [W ; W_msg] + b )
// Stacked weight (256x128) in smem; A tile 64x256 transposed in smem.
// Microkernel uses packed f32x2 FFMA: 16 FFMA2 per k per thread.
// ---------------------------------------------------------------------------
#define MT     64
#define SA_LD  66   // even: keeps float2 A-loads 8B-aligned
#define SMEM_GEMM ((256 * 128 + 256 * SA_LD) * (int)sizeof(float))  // 198,656 B

__global__ __launch_bounds__(256, 1)
void k_gemm(const float* __restrict__ W_msg,
            const float* __restrict__ W,
            const float* __restrict__ b,
            float* __restrict__ out) {
    extern __shared__ float smem[];
    float* sW = smem;              // [256][128]
    float* sA = smem + 256 * 128;  // [256][SA_LD]

    const int tid = threadIdx.x;
    const int tileBase = blockIdx.x * MT;

    // stacked weights: k 0..127 = W, 128..255 = W_msg
    {
        const float4* W4  = reinterpret_cast<const float4*>(W);
        const float4* Wm4 = reinterpret_cast<const float4*>(W_msg);
        float4* sW4 = reinterpret_cast<float4*>(sW);
        #pragma unroll
        for (int i = tid; i < 256 * 32; i += 256)
            sW4[i] = (i < 128 * 32) ? __ldg(W4 + i) : __ldg(Wm4 + (i - 128 * 32));
    }

    // A tile transposed: k 0..127 = hn, k 128..255 = agg (norm pre-applied)
    for (int i = tid; i < MT * 32; i += 256) {
        int rr = i / 32, k4 = i % 32;
        int row = tileBase + rr;
        float4 v = make_float4(0.f, 0.f, 0.f, 0.f);
        if (row < N_NODES) v = reinterpret_cast<const float4*>(g_hn)[row * D4 + k4];
        sA[(k4 * 4 + 0) * SA_LD + rr] = v.x;
        sA[(k4 * 4 + 1) * SA_LD + rr] = v.y;
        sA[(k4 * 4 + 2) * SA_LD + rr] = v.z;
        sA[(k4 * 4 + 3) * SA_LD + rr] = v.w;
    }
    for (int i = tid; i < MT * 32; i += 256) {
        int rr = i / 32, k4 = i % 32;
        int row = tileBase + rr;
        float4 v = make_float4(0.f, 0.f, 0.f, 0.f);
        if (row < N_NODES) v = reinterpret_cast<const float4*>(g_agg)[row * D4 + k4];
        sA[(128 + k4 * 4 + 0) * SA_LD + rr] = v.x;
        sA[(128 + k4 * 4 + 1) * SA_LD + rr] = v.y;
        sA[(128 + k4 * 4 + 2) * SA_LD + rr] = v.z;
        sA[(128 + k4 * 4 + 3) * SA_LD + rr] = v.w;
    }
    __syncthreads();

    const int tcol = tid & 15;    // 16 col groups of 4 (x2 halves)
    const int trow = tid >> 4;    // 16 row groups of 4
    const int r0 = trow * 4;

    u64 acc[4][4];                // [row][colpair]
    #pragma unroll
    for (int rr = 0; rr < 4; rr++)
        #pragma unroll
        for (int cp = 0; cp < 4; cp++) acc[rr][cp] = 0ull;

    #pragma unroll 4
    for (int k = 0; k < 256; k++) {
        ulonglong2 w0 = *reinterpret_cast<const ulonglong2*>(&sW[k * 128 + tcol * 4]);
        ulonglong2 w1 = *reinterpret_cast<const ulonglong2*>(&sW[k * 128 + 64 + tcol * 4]);
        float2 a01 = *reinterpret_cast<const float2*>(&sA[k * SA_LD + r0]);
        float2 a23 = *reinterpret_cast<const float2*>(&sA[k * SA_LD + r0 + 2]);
        u64 ad[4];
        ad[0] = pack_dup(a01.x);
        ad[1] = pack_dup(a01.y);
        ad[2] = pack_dup(a23.x);
        ad[3] = pack_dup(a23.y);
        #pragma unroll
        for (int rr = 0; rr < 4; rr++) {
            acc[rr][0] = ffma2(ad[rr], w0.x, acc[rr][0]);
            acc[rr][1] = ffma2(ad[rr], w0.y, acc[rr][1]);
            acc[rr][2] = ffma2(ad[rr], w1.x, acc[rr][2]);
            acc[rr][3] = ffma2(ad[rr], w1.y, acc[rr][3]);
        }
    }

    // epilogue: + b, relu, store
    const int c0 = tcol * 4;
    float4 b0 = __ldg(reinterpret_cast<const float4*>(b) + c0 / 4);
    float4 b1 = __ldg(reinterpret_cast<const float4*>(b) + (c0 + 64) / 4);
    #pragma unroll
    for (int rr = 0; rr < 4; rr++) {
        int row = tileBase + r0 + rr;
        if (row >= N_NODES) break;
        float2 p0 = unpack2(acc[rr][0]);
        float2 p1 = unpack2(acc[rr][1]);
        float2 p2 = unpack2(acc[rr][2]);
        float2 p3 = unpack2(acc[rr][3]);
        float4 o0, o1;
        o0.x = fmaxf(p0.x + b0.x, 0.f);
        o0.y = fmaxf(p0.y + b0.y, 0.f);
        o0.z = fmaxf(p1.x + b0.z, 0.f);
        o0.w = fmaxf(p1.y + b0.w, 0.f);
        o1.x = fmaxf(p2.x + b1.x, 0.f);
        o1.y = fmaxf(p2.y + b1.y, 0.f);
        o1.z = fmaxf(p3.x + b1.z, 0.f);
        o1.w = fmaxf(p3.y + b1.w, 0.f);
        reinterpret_cast<float4*>(out)[row * D4 + c0 / 4] = o0;
        reinterpret_cast<float4*>(out)[row * D4 + (c0 + 64) / 4] = o1;
    }
}

// ---------------------------------------------------------------------------
extern "C" void kernel_launch(void* const* d_in, const int* in_sizes, int n_in,
                              void* d_out, int out_size) {
    const float* h     = (const float*)d_in[0];
    const float* r     = (const float*)d_in[1];
    const float* norm  = (const float*)d_in[2];
    const int*   src   = (const int*)d_in[3];
    const int*   dst   = (const int*)d_in[4];
    const int*   rel   = (const int*)d_in[5];
    const float* W_msg = (const float*)d_in[6];
    const float* W     = (const float*)d_in[7];
    const float* b     = (const float*)d_in[8];
    float* out = (float*)d_out;

    // prep: hn = h*norm, zero counters
    k_prep<<<(N_NODES * D4 + 255) / 256, 256>>>(h, norm);

    // CSR build
    k_hist<<<(N_EDGES + 255) / 256, 256>>>(dst);
    k_scan1<<<N_CHUNKS, SCAN_CHUNK>>>();
    k_scan2<<<1, 32>>>();
    k_scan3<<<N_CHUNKS, SCAN_CHUNK>>>();
    k_fill<<<(N_EDGES + 255) / 256, 256>>>(src, dst, rel);

    // gather (one warp per node)
    k_gather<<<(N_NODES * 32 + 255) / 256, 256>>>(r, norm);

    // fused GEMM + epilogue
    cudaFuncSetAttribute(k_gemm, cudaFuncAttributeMaxDynamicSharedMemorySize, SMEM_GEMM);
    k_gemm<<<(N_NODES + MT - 1) / MT, 256, SMEM_GEMM>>>(W_msg, W, b, out);
}